// round 4
// baseline (speedup 1.0000x reference)
#include <cuda_runtime.h>
#include <cuda_bf16.h>
#include <math.h>
#include <stdint.h>

#define N_NODES 100000
#define E_EDGES 1600000
#define C_DIM 256
#define H_DIM 128
#define F_DIM 64

// Scratch (__device__ globals; no allocation allowed)
__device__ float         g_buf1[N_NODES * H_DIM];       // GEMM fp32 outputs
__device__ __nv_bfloat16 g_Xh[N_NODES * C_DIM];
__device__ __nv_bfloat16 g_Xl[N_NODES * C_DIM];
__device__ __nv_bfloat16 g_Zh[N_NODES * H_DIM];
__device__ __nv_bfloat16 g_Zl[N_NODES * H_DIM];
__device__ __nv_bfloat16 g_Wh[57344];                   // W0 | Wh0 | W1
__device__ __nv_bfloat16 g_Wl[57344];
__device__ int           g_rowptr[N_NODES + 1];

// ---------------------------------------------------------------------------
// Helpers
// ---------------------------------------------------------------------------
__device__ __forceinline__ uint32_t smem_u32(const void* p) {
    uint32_t a;
    asm("{ .reg .u64 t; cvta.to.shared.u64 t, %1; cvt.u32.u64 %0, t; }" : "=r"(a) : "l"(p));
    return a;
}
__device__ __forceinline__ void ldsm_x4(uint32_t (&r)[4], uint32_t addr) {
    asm volatile("ldmatrix.sync.aligned.m8n8.x4.shared.b16 {%0,%1,%2,%3}, [%4];"
                 : "=r"(r[0]), "=r"(r[1]), "=r"(r[2]), "=r"(r[3]) : "r"(addr));
}
__device__ __forceinline__ void mma_bf16(float (&d)[4], const uint32_t (&a)[4],
                                         uint32_t b0, uint32_t b1) {
    asm volatile(
        "mma.sync.aligned.m16n8k16.row.col.f32.bf16.bf16.f32 "
        "{%0,%1,%2,%3}, {%4,%5,%6,%7}, {%8,%9}, {%0,%1,%2,%3};"
        : "+f"(d[0]), "+f"(d[1]), "+f"(d[2]), "+f"(d[3])
        : "r"(a[0]), "r"(a[1]), "r"(a[2]), "r"(a[3]), "r"(b0), "r"(b1));
}
__device__ __forceinline__ void cp_async16(uint32_t dst, const void* src, int srcsize) {
    asm volatile("cp.async.cg.shared.global [%0], [%1], 16, %2;"
                 :: "r"(dst), "l"(src), "r"(srcsize));
}
#define CP_COMMIT() asm volatile("cp.async.commit_group;" ::: "memory")
template<int NW> __device__ __forceinline__ void cp_wait() {
    asm volatile("cp.async.wait_group %0;" :: "n"(NW) : "memory");
}

// float4 -> (hi bf16x2 pair, lo bf16x2 pair)
__device__ __forceinline__ void split4(float4 v, uint2& hv, uint2& lv) {
    __nv_bfloat16 h0 = __float2bfloat16(v.x);
    __nv_bfloat16 h1 = __float2bfloat16(v.y);
    __nv_bfloat16 h2 = __float2bfloat16(v.z);
    __nv_bfloat16 h3 = __float2bfloat16(v.w);
    __nv_bfloat16 l0 = __float2bfloat16(v.x - __bfloat162float(h0));
    __nv_bfloat16 l1 = __float2bfloat16(v.y - __bfloat162float(h1));
    __nv_bfloat16 l2 = __float2bfloat16(v.z - __bfloat162float(h2));
    __nv_bfloat16 l3 = __float2bfloat16(v.w - __bfloat162float(h3));
    __nv_bfloat162 hp0(h0, h1), hp1(h2, h3), lp0(l0, l1), lp1(l2, l3);
    hv = make_uint2(*reinterpret_cast<uint32_t*>(&hp0), *reinterpret_cast<uint32_t*>(&hp1));
    lv = make_uint2(*reinterpret_cast<uint32_t*>(&lp0), *reinterpret_cast<uint32_t*>(&lp1));
}

// ---------------------------------------------------------------------------
// Row-pointer build + fp32 -> bf16 hi/lo splitter
// ---------------------------------------------------------------------------
__global__ void rowptr_kernel(const int* __restrict__ edge_row) {
    int i = blockIdx.x * blockDim.x + threadIdx.x;
    if (i > N_NODES) return;
    int lo = 0, hi = E_EDGES;
    while (lo < hi) {
        int mid = (lo + hi) >> 1;
        if (edge_row[mid] < i) lo = mid + 1;
        else hi = mid;
    }
    g_rowptr[i] = lo;
}

__global__ void split_kernel(const float* __restrict__ src,
                             __nv_bfloat16* __restrict__ hi,
                             __nv_bfloat16* __restrict__ lo, int n4) {
    int i = blockIdx.x * blockDim.x + threadIdx.x;
    if (i >= n4) return;
    float4 v = reinterpret_cast<const float4*>(src)[i];
    uint2 hv, lv;
    split4(v, hv, lv);
    reinterpret_cast<uint2*>(hi)[i] = hv;
    reinterpret_cast<uint2*>(lo)[i] = lv;
}

// ---------------------------------------------------------------------------
// bf16 tensor-core GEMM, cp.async double-buffered:
//   out[m][n] = sum_k (Ah+Al)[m][k] * (Wh+Wl)[n][k]   (3-pass split MMA)
// BM=128, BK=64, 256 threads. Smem rows: 64 bf16 + 8 pad = 144B stride.
// ---------------------------------------------------------------------------
template<int N, int K>
__global__ void __launch_bounds__(256) gemm_bf16(const __nv_bfloat16* __restrict__ Ah,
                                                 const __nv_bfloat16* __restrict__ Al,
                                                 const __nv_bfloat16* __restrict__ Wh,
                                                 const __nv_bfloat16* __restrict__ Wl,
                                                 float* __restrict__ out, int M) {
    constexpr int BM = 128;
    constexpr int BK = 64;
    constexpr int NC = K / BK;
    constexpr int LDS = 144;                    // bytes per smem row
    constexpr int ABYTES = BM * LDS;            // 18432
    constexpr int WBYTES = N * LDS;
    constexpr int STAGE  = 2 * ABYTES + 2 * WBYTES;
    constexpr int WCOLS = N / 32;
    constexpr int WROWS = 8 / WCOLS;
    constexpr int WTM = BM / WROWS;
    constexpr int MT = WTM / 16;

    extern __shared__ char smem[];
    const uint32_t sb = smem_u32(smem);

    const int tid  = threadIdx.x;
    const int wid  = tid >> 5;
    const int lane = tid & 31;
    const int wm   = (wid / WCOLS) * WTM;
    const int wn   = (wid % WCOLS) * 32;
    const int bm   = blockIdx.x * BM;
    const int arows = min(BM, M - bm);

    const int lrow  = lane & 15;
    const int lcolb = (lane >> 4) * 16;

    float acc[MT][4][4];
#pragma unroll
    for (int i = 0; i < MT; i++)
#pragma unroll
        for (int j = 0; j < 4; j++)
#pragma unroll
            for (int c = 0; c < 4; c++) acc[i][j][c] = 0.f;

    // stage fill: cp.async all four tiles of chunk k0 into stage s
    auto fill = [&](int s, int k0) {
        const uint32_t base = sb + s * STAGE;
#pragma unroll
        for (int idx = tid; idx < BM * 8; idx += 256) {       // 4 iters
            int row = idx >> 3, c = idx & 7;
            int sz = (row < arows) ? 16 : 0;
            size_t go = (size_t)(bm + row) * K + k0 + c * 8;
            uint32_t so = (uint32_t)(row * LDS + c * 16);
            cp_async16(base + so, Ah + go, sz);
            cp_async16(base + ABYTES + so, Al + go, sz);
        }
#pragma unroll
        for (int idx = tid; idx < N * 8; idx += 256) {        // 4 or 2 iters
            int row = idx >> 3, c = idx & 7;
            size_t go = (size_t)row * K + k0 + c * 8;
            uint32_t so = (uint32_t)(row * LDS + c * 16);
            cp_async16(base + 2 * ABYTES + so, Wh + go, 16);
            cp_async16(base + 2 * ABYTES + WBYTES + so, Wl + go, 16);
        }
        CP_COMMIT();
    };

    fill(0, 0);

    for (int kc = 0; kc < NC; kc++) {
        if (kc + 1 < NC) fill((kc + 1) & 1, (kc + 1) * BK);
        if (kc + 1 < NC) cp_wait<1>(); else cp_wait<0>();
        __syncthreads();

        const uint32_t st = sb + (kc & 1) * STAGE;
        const uint32_t aH = st, aL = st + ABYTES;
        const uint32_t wH = st + 2 * ABYTES, wL = wH + WBYTES;

#pragma unroll
        for (int ks = 0; ks < 4; ks++) {
            const uint32_t cb = (uint32_t)(ks * 32 + lcolb);
            uint32_t afh[MT][4], afl[MT][4];
#pragma unroll
            for (int mt = 0; mt < MT; mt++) {
                uint32_t ro = (uint32_t)((wm + mt * 16 + lrow) * LDS) + cb;
                ldsm_x4(afh[mt], aH + ro);
                ldsm_x4(afl[mt], aL + ro);
            }
            uint32_t bfh[2][4], bfl[2][4];
#pragma unroll
            for (int np = 0; np < 2; np++) {
                uint32_t ro = (uint32_t)((wn + np * 16 + lrow) * LDS) + cb;
                ldsm_x4(bfh[np], wH + ro);
                ldsm_x4(bfl[np], wL + ro);
            }
#pragma unroll
            for (int mt = 0; mt < MT; mt++) {
#pragma unroll
                for (int nt = 0; nt < 4; nt++) {
                    int np = nt >> 1, h = nt & 1;
                    mma_bf16(acc[mt][nt], afh[mt], bfh[np][h], bfh[np][h + 2]);
                    mma_bf16(acc[mt][nt], afl[mt], bfh[np][h], bfh[np][h + 2]);
                    mma_bf16(acc[mt][nt], afh[mt], bfl[np][h], bfl[np][h + 2]);
                }
            }
        }
        __syncthreads();
    }

    // Epilogue
#pragma unroll
    for (int mt = 0; mt < MT; mt++) {
#pragma unroll
        for (int nt = 0; nt < 4; nt++) {
            int r0 = wm + mt * 16 + (lane >> 2);
            int c0 = wn + nt * 8 + (lane & 3) * 2;
            if (r0 < arows)
                *reinterpret_cast<float2*>(&out[(size_t)(bm + r0) * N + c0]) =
                    make_float2(acc[mt][nt][0], acc[mt][nt][1]);
            if (r0 + 8 < arows)
                *reinterpret_cast<float2*>(&out[(size_t)(bm + r0 + 8) * N + c0]) =
                    make_float2(acc[mt][nt][2], acc[mt][nt][3]);
        }
    }
}

// ---------------------------------------------------------------------------
// SpMM (H=128): warp/row, fp32 accumulate, ReLU, emits bf16 hi/lo split
// ---------------------------------------------------------------------------
__global__ void __launch_bounds__(256) spmm128_split_kernel(const int* __restrict__ edge_col,
                                                            const float* __restrict__ edge_val,
                                                            const float* __restrict__ Z,
                                                            __nv_bfloat16* __restrict__ Oh,
                                                            __nv_bfloat16* __restrict__ Ol) {
    int gw   = (blockIdx.x * blockDim.x + threadIdx.x) >> 5;
    int lane = threadIdx.x & 31;
    if (gw >= N_NODES) return;
    int s = g_rowptr[gw];
    int e = g_rowptr[gw + 1];

    float4 acc = make_float4(0.f, 0.f, 0.f, 0.f);
    for (int i = s; i < e; i++) {
        int   col = __ldg(&edge_col[i]);
        float val = __ldg(&edge_val[i]);
        float4 z = *reinterpret_cast<const float4*>(&Z[(size_t)col * H_DIM + lane * 4]);
        acc.x = fmaf(val, z.x, acc.x);
        acc.y = fmaf(val, z.y, acc.y);
        acc.z = fmaf(val, z.z, acc.z);
        acc.w = fmaf(val, z.w, acc.w);
    }
    acc.x = fmaxf(acc.x, 0.f);
    acc.y = fmaxf(acc.y, 0.f);
    acc.z = fmaxf(acc.z, 0.f);
    acc.w = fmaxf(acc.w, 0.f);
    uint2 hv, lv;
    split4(acc, hv, lv);
    size_t o = (size_t)gw * (H_DIM / 4) + lane;
    reinterpret_cast<uint2*>(Oh)[o] = hv;
    reinterpret_cast<uint2*>(Ol)[o] = lv;
}

// ---------------------------------------------------------------------------
// Final SpMM (F=64) fused with row softmax
// ---------------------------------------------------------------------------
__global__ void __launch_bounds__(256) spmm64_softmax_kernel(const int* __restrict__ edge_col,
                                                             const float* __restrict__ edge_val,
                                                             const float* __restrict__ Z,
                                                             float* __restrict__ out) {
    int gw   = (blockIdx.x * blockDim.x + threadIdx.x) >> 5;
    int lane = threadIdx.x & 31;
    if (gw >= N_NODES) return;
    int s = g_rowptr[gw];
    int e = g_rowptr[gw + 1];

    float a0 = 0.f, a1 = 0.f;
    for (int i = s; i < e; i++) {
        int   col = __ldg(&edge_col[i]);
        float val = __ldg(&edge_val[i]);
        float2 z = *reinterpret_cast<const float2*>(&Z[(size_t)col * F_DIM + lane * 2]);
        a0 = fmaf(val, z.x, a0);
        a1 = fmaf(val, z.y, a1);
    }
    float m = fmaxf(a0, a1);
#pragma unroll
    for (int off = 16; off > 0; off >>= 1)
        m = fmaxf(m, __shfl_xor_sync(0xFFFFFFFFu, m, off));
    float e0 = expf(a0 - m);
    float e1 = expf(a1 - m);
    float ssum = e0 + e1;
#pragma unroll
    for (int off = 16; off > 0; off >>= 1)
        ssum += __shfl_xor_sync(0xFFFFFFFFu, ssum, off);
    float inv = 1.0f / ssum;
    *reinterpret_cast<float2*>(&out[(size_t)gw * F_DIM + lane * 2]) =
        make_float2(e0 * inv, e1 * inv);
}

// ---------------------------------------------------------------------------
// Launch
// ---------------------------------------------------------------------------
extern "C" void kernel_launch(void* const* d_in, const int* in_sizes, int n_in,
                              void* d_out, int out_size) {
    const float* X        = (const float*)d_in[0];
    const int*   edge_row = (const int*)d_in[1];
    const int*   edge_col = (const int*)d_in[2];
    const float* edge_val = (const float*)d_in[3];
    const float* W0       = (const float*)d_in[4];
    const float* Wh0      = (const float*)d_in[5];
    const float* W1       = (const float*)d_in[6];
    float*       out      = (float*)d_out;

    float *buf1;
    __nv_bfloat16 *Xh, *Xl, *Zh, *Zl, *Wh, *Wl;
    cudaGetSymbolAddress((void**)&buf1, g_buf1);
    cudaGetSymbolAddress((void**)&Xh, g_Xh);
    cudaGetSymbolAddress((void**)&Xl, g_Xl);
    cudaGetSymbolAddress((void**)&Zh, g_Zh);
    cudaGetSymbolAddress((void**)&Zl, g_Zl);
    cudaGetSymbolAddress((void**)&Wh, g_Wh);
    cudaGetSymbolAddress((void**)&Wl, g_Wl);

    constexpr int SMEM_128 = 2 * (2 * 128 * 144 + 2 * 128 * 144);  // 147456
    constexpr int SMEM_64  = 2 * (2 * 128 * 144 + 2 * 64 * 144);   // 110592
    cudaFuncSetAttribute(gemm_bf16<128, 256>, cudaFuncAttributeMaxDynamicSharedMemorySize, SMEM_128);
    cudaFuncSetAttribute(gemm_bf16<128, 128>, cudaFuncAttributeMaxDynamicSharedMemorySize, SMEM_128);
    cudaFuncSetAttribute(gemm_bf16<64, 128>,  cudaFuncAttributeMaxDynamicSharedMemorySize, SMEM_64);

    const int gemm_grid = (N_NODES + 127) / 128;       // 782
    const int spmm_grid = (N_NODES * 32 + 255) / 256;  // 12500

    rowptr_kernel<<<(N_NODES + 1 + 255) / 256, 256>>>(edge_row);

    // Split inputs to bf16 hi/lo
    split_kernel<<<(N_NODES * C_DIM / 4 + 255) / 256, 256>>>(X, Xh, Xl, N_NODES * C_DIM / 4);
    split_kernel<<<(32768 / 4 + 255) / 256, 256>>>(W0,  Wh,         Wl,         32768 / 4);
    split_kernel<<<(16384 / 4 + 255) / 256, 256>>>(Wh0, Wh + 32768, Wl + 32768, 16384 / 4);
    split_kernel<<<(8192 / 4 + 255) / 256, 256>>>(W1,  Wh + 49152, Wl + 49152, 8192 / 4);

    // Layer 0
    gemm_bf16<128, 256><<<gemm_grid, 256, SMEM_128>>>(Xh, Xl, Wh, Wl, buf1, N_NODES);
    spmm128_split_kernel<<<spmm_grid, 256>>>(edge_col, edge_val, buf1, Zh, Zl);

    // Hidden layer
    gemm_bf16<128, 128><<<gemm_grid, 256, SMEM_128>>>(Zh, Zl, Wh + 32768, Wl + 32768, buf1, N_NODES);
    spmm128_split_kernel<<<spmm_grid, 256>>>(edge_col, edge_val, buf1, Zh, Zl);

    // Output layer
    gemm_bf16<64, 128><<<gemm_grid, 256, SMEM_64>>>(Zh, Zl, Wh + 49152, Wl + 49152, buf1, N_NODES);
    spmm64_softmax_kernel<<<spmm_grid, 256>>>(edge_col, edge_val, buf1, out);
}

// round 5
// speedup vs baseline: 1.1625x; 1.1625x over previous
#include <cuda_runtime.h>
#include <cuda_bf16.h>
#include <math.h>
#include <stdint.h>

#define N_NODES 100000
#define E_EDGES 1600000
#define C_DIM 256
#define H_DIM 128
#define F_DIM 64

// Scratch (__device__ globals; no allocation allowed)
__device__ float g_buf1[N_NODES * H_DIM];
__device__ float g_buf2[N_NODES * H_DIM];
__device__ int   g_rowptr[N_NODES + 1];

// ---------------------------------------------------------------------------
// Helpers
// ---------------------------------------------------------------------------
__device__ __forceinline__ uint32_t f2tf32(float f) {
    uint32_t o;
    asm("cvt.rna.tf32.f32 %0, %1;" : "=r"(o) : "f"(f));
    return o;
}
__device__ __forceinline__ void mma_tf32(float (&d)[4], const uint32_t (&a)[4],
                                         uint32_t b0, uint32_t b1) {
    asm volatile(
        "mma.sync.aligned.m16n8k8.row.col.f32.tf32.tf32.f32 "
        "{%0,%1,%2,%3}, {%4,%5,%6,%7}, {%8,%9}, {%0,%1,%2,%3};"
        : "+f"(d[0]), "+f"(d[1]), "+f"(d[2]), "+f"(d[3])
        : "r"(a[0]), "r"(a[1]), "r"(a[2]), "r"(a[3]), "r"(b0), "r"(b1));
}

// ---------------------------------------------------------------------------
// Row-pointer build: lower_bound over sorted edge_row
// ---------------------------------------------------------------------------
__global__ void rowptr_kernel(const int* __restrict__ edge_row) {
    int i = blockIdx.x * blockDim.x + threadIdx.x;
    if (i > N_NODES) return;
    int lo = 0, hi = E_EDGES;
    while (lo < hi) {
        int mid = (lo + hi) >> 1;
        if (edge_row[mid] < i) lo = mid + 1;
        else hi = mid;
    }
    g_rowptr[i] = lo;
}

// ---------------------------------------------------------------------------
// tf32 tensor-core GEMM (single pass):
//   out[m][n] = sum_k A[m][k] * W[n][k]
// BM=128, BK=32, 256 threads (8 warps).
// N=128: warp grid 2x4 (warp tile 64x32, MT=4). N=64: 4x2 (32x32, MT=2).
// Smem rows: 36 floats (144B) stride -> bank = (4r+c)%32, conflict-free
// for both the A-fragment and B-fragment LDS patterns.
// ---------------------------------------------------------------------------
template<int N, int K>
__global__ void __launch_bounds__(256) gemm_tf32(const float* __restrict__ A,
                                                 const float* __restrict__ W,
                                                 float* __restrict__ out, int M) {
    constexpr int BM = 128;
    constexpr int LDS = 36;                    // floats per smem row
    constexpr int WCOLS = N / 32;              // warps along N
    constexpr int WROWS = 8 / WCOLS;
    constexpr int WTM = BM / WROWS;            // 64 or 32
    constexpr int MT = WTM / 16;               // 4 or 2

    __shared__ float sA[BM * LDS];
    __shared__ float sW[N * LDS];
    const uint32_t* sAu = reinterpret_cast<const uint32_t*>(sA);
    const uint32_t* sWu = reinterpret_cast<const uint32_t*>(sW);

    const int tid  = threadIdx.x;
    const int wid  = tid >> 5;
    const int lane = tid & 31;
    const int wm   = (wid / WCOLS) * WTM;
    const int wn   = (wid % WCOLS) * 32;
    const int bm   = blockIdx.x * BM;
    const int arows = min(BM, M - bm);

    const int fr = lane >> 2;                  // fragment row within 8
    const int fc = lane & 3;                   // fragment col within 4

    float acc[MT][4][4];
#pragma unroll
    for (int i = 0; i < MT; i++)
#pragma unroll
        for (int j = 0; j < 4; j++)
#pragma unroll
            for (int c = 0; c < 4; c++) acc[i][j][c] = 0.f;

    for (int k0 = 0; k0 < K; k0 += 32) {
        // Stage A chunk [128 x 32], tf32-rounded
#pragma unroll
        for (int idx = tid; idx < BM * 8; idx += 256) {
            int row = idx >> 3, g = idx & 7;
            float4 v = make_float4(0.f, 0.f, 0.f, 0.f);
            if (row < arows)
                v = *reinterpret_cast<const float4*>(&A[(size_t)(bm + row) * K + k0 + g * 4]);
            uint4 t = make_uint4(f2tf32(v.x), f2tf32(v.y), f2tf32(v.z), f2tf32(v.w));
            *reinterpret_cast<uint4*>(&sA[row * LDS + g * 4]) = t;
        }
        // Stage W chunk [N x 32]
#pragma unroll
        for (int idx = tid; idx < N * 8; idx += 256) {
            int row = idx >> 3, g = idx & 7;
            float4 v = *reinterpret_cast<const float4*>(&W[(size_t)row * K + k0 + g * 4]);
            uint4 t = make_uint4(f2tf32(v.x), f2tf32(v.y), f2tf32(v.z), f2tf32(v.w));
            *reinterpret_cast<uint4*>(&sW[row * LDS + g * 4]) = t;
        }
        __syncthreads();

#pragma unroll
        for (int ks = 0; ks < 4; ks++) {
            const int kb = ks * 8 + fc;
            uint32_t af[MT][4];
#pragma unroll
            for (int mt = 0; mt < MT; mt++) {
                int base = (wm + mt * 16 + fr) * LDS + kb;
                af[mt][0] = sAu[base];
                af[mt][1] = sAu[base + 8 * LDS];
                af[mt][2] = sAu[base + 4];
                af[mt][3] = sAu[base + 8 * LDS + 4];
            }
            uint32_t bf[4][2];
#pragma unroll
            for (int nt = 0; nt < 4; nt++) {
                int base = (wn + nt * 8 + fr) * LDS + kb;
                bf[nt][0] = sWu[base];
                bf[nt][1] = sWu[base + 4];
            }
#pragma unroll
            for (int mt = 0; mt < MT; mt++)
#pragma unroll
                for (int nt = 0; nt < 4; nt++)
                    mma_tf32(acc[mt][nt], af[mt], bf[nt][0], bf[nt][1]);
        }
        __syncthreads();
    }

    // Epilogue: mma d-frag layout -> global
#pragma unroll
    for (int mt = 0; mt < MT; mt++) {
#pragma unroll
        for (int nt = 0; nt < 4; nt++) {
            int r0 = wm + mt * 16 + fr;
            int c0 = wn + nt * 8 + fc * 2;
            if (r0 < arows)
                *reinterpret_cast<float2*>(&out[(size_t)(bm + r0) * N + c0]) =
                    make_float2(acc[mt][nt][0], acc[mt][nt][1]);
            if (r0 + 8 < arows)
                *reinterpret_cast<float2*>(&out[(size_t)(bm + r0 + 8) * N + c0]) =
                    make_float2(acc[mt][nt][2], acc[mt][nt][3]);
        }
    }
}

// ---------------------------------------------------------------------------
// SpMM (H=128): one warp per row, float4 per lane, ReLU
// ---------------------------------------------------------------------------
template<bool RELU>
__global__ void __launch_bounds__(256) spmm128_kernel(const int* __restrict__ edge_col,
                                                      const float* __restrict__ edge_val,
                                                      const float* __restrict__ Z,
                                                      float* __restrict__ out) {
    int gw   = (blockIdx.x * blockDim.x + threadIdx.x) >> 5;
    int lane = threadIdx.x & 31;
    if (gw >= N_NODES) return;
    int s = g_rowptr[gw];
    int e = g_rowptr[gw + 1];

    float4 acc = make_float4(0.f, 0.f, 0.f, 0.f);
    for (int i = s; i < e; i++) {
        int   col = __ldg(&edge_col[i]);
        float val = __ldg(&edge_val[i]);
        float4 z = *reinterpret_cast<const float4*>(&Z[(size_t)col * H_DIM + lane * 4]);
        acc.x = fmaf(val, z.x, acc.x);
        acc.y = fmaf(val, z.y, acc.y);
        acc.z = fmaf(val, z.z, acc.z);
        acc.w = fmaf(val, z.w, acc.w);
    }
    if (RELU) {
        acc.x = fmaxf(acc.x, 0.f);
        acc.y = fmaxf(acc.y, 0.f);
        acc.z = fmaxf(acc.z, 0.f);
        acc.w = fmaxf(acc.w, 0.f);
    }
    *reinterpret_cast<float4*>(&out[(size_t)gw * H_DIM + lane * 4]) = acc;
}

// ---------------------------------------------------------------------------
// Final SpMM (F=64) fused with row softmax
// ---------------------------------------------------------------------------
__global__ void __launch_bounds__(256) spmm64_softmax_kernel(const int* __restrict__ edge_col,
                                                             const float* __restrict__ edge_val,
                                                             const float* __restrict__ Z,
                                                             float* __restrict__ out) {
    int gw   = (blockIdx.x * blockDim.x + threadIdx.x) >> 5;
    int lane = threadIdx.x & 31;
    if (gw >= N_NODES) return;
    int s = g_rowptr[gw];
    int e = g_rowptr[gw + 1];

    float a0 = 0.f, a1 = 0.f;
    for (int i = s; i < e; i++) {
        int   col = __ldg(&edge_col[i]);
        float val = __ldg(&edge_val[i]);
        float2 z = *reinterpret_cast<const float2*>(&Z[(size_t)col * F_DIM + lane * 2]);
        a0 = fmaf(val, z.x, a0);
        a1 = fmaf(val, z.y, a1);
    }
    float m = fmaxf(a0, a1);
#pragma unroll
    for (int off = 16; off > 0; off >>= 1)
        m = fmaxf(m, __shfl_xor_sync(0xFFFFFFFFu, m, off));
    float e0 = expf(a0 - m);
    float e1 = expf(a1 - m);
    float ssum = e0 + e1;
#pragma unroll
    for (int off = 16; off > 0; off >>= 1)
        ssum += __shfl_xor_sync(0xFFFFFFFFu, ssum, off);
    float inv = 1.0f / ssum;
    *reinterpret_cast<float2*>(&out[(size_t)gw * F_DIM + lane * 2]) =
        make_float2(e0 * inv, e1 * inv);
}

// ---------------------------------------------------------------------------
// Launch
// ---------------------------------------------------------------------------
extern "C" void kernel_launch(void* const* d_in, const int* in_sizes, int n_in,
                              void* d_out, int out_size) {
    const float* X        = (const float*)d_in[0];
    const int*   edge_row = (const int*)d_in[1];
    const int*   edge_col = (const int*)d_in[2];
    const float* edge_val = (const float*)d_in[3];
    const float* W0       = (const float*)d_in[4];
    const float* Wh0      = (const float*)d_in[5];
    const float* W1       = (const float*)d_in[6];
    float*       out      = (float*)d_out;

    float *buf1, *buf2;
    cudaGetSymbolAddress((void**)&buf1, g_buf1);
    cudaGetSymbolAddress((void**)&buf2, g_buf2);

    const int gemm_grid = (N_NODES + 127) / 128;       // 782
    const int spmm_grid = (N_NODES * 32 + 255) / 256;  // 12500

    rowptr_kernel<<<(N_NODES + 1 + 255) / 256, 256>>>(edge_row);

    // Layer 0: buf1 = X @ W0^T ; buf2 = relu(A @ buf1)
    gemm_tf32<128, 256><<<gemm_grid, 256>>>(X, W0, buf1, N_NODES);
    spmm128_kernel<true><<<spmm_grid, 256>>>(edge_col, edge_val, buf1, buf2);

    // Hidden: buf1 = buf2 @ Wh0^T ; buf2 = relu(A @ buf1)
    gemm_tf32<128, 128><<<gemm_grid, 256>>>(buf2, Wh0, buf1, N_NODES);
    spmm128_kernel<true><<<spmm_grid, 256>>>(edge_col, edge_val, buf1, buf2);

    // Output: buf1 = buf2 @ W1^T ; out = softmax(A @ buf1)
    gemm_tf32<64, 128><<<gemm_grid, 256>>>(buf2, W1, buf1, N_NODES);
    spmm64_softmax_kernel<<<spmm_grid, 256>>>(edge_col, edge_val, buf1, out);
}

// round 6
// speedup vs baseline: 1.2962x; 1.1150x over previous
#include <cuda_runtime.h>
#include <cuda_bf16.h>
#include <math.h>
#include <stdint.h>

#define N_NODES 100000
#define E_EDGES 1600000
#define C_DIM 256
#define H_DIM 128
#define F_DIM 64

// Scratch (__device__ globals; no allocation allowed)
__device__ float g_buf1[N_NODES * H_DIM];
__device__ float g_buf2[N_NODES * H_DIM];
__device__ int   g_rowptr[N_NODES + 1];

// ---------------------------------------------------------------------------
// Helpers
// ---------------------------------------------------------------------------
__device__ __forceinline__ uint32_t smem_u32(const void* p) {
    uint32_t a;
    asm("{ .reg .u64 t; cvta.to.shared.u64 t, %1; cvt.u32.u64 %0, t; }" : "=r"(a) : "l"(p));
    return a;
}
__device__ __forceinline__ uint32_t f2tf32(float f) {
    uint32_t o;
    asm("cvt.rna.tf32.f32 %0, %1;" : "=r"(o) : "f"(f));
    return o;
}
__device__ __forceinline__ void mma_tf32(float (&d)[4], const uint32_t (&a)[4],
                                         uint32_t b0, uint32_t b1) {
    asm volatile(
        "mma.sync.aligned.m16n8k8.row.col.f32.tf32.tf32.f32 "
        "{%0,%1,%2,%3}, {%4,%5,%6,%7}, {%8,%9}, {%0,%1,%2,%3};"
        : "+f"(d[0]), "+f"(d[1]), "+f"(d[2]), "+f"(d[3])
        : "r"(a[0]), "r"(a[1]), "r"(a[2]), "r"(a[3]), "r"(b0), "r"(b1));
}
__device__ __forceinline__ void cp_async16(uint32_t dst, const void* src, int srcsize) {
    asm volatile("cp.async.cg.shared.global [%0], [%1], 16, %2;"
                 :: "r"(dst), "l"(src), "r"(srcsize));
}
#define CP_COMMIT() asm volatile("cp.async.commit_group;" ::: "memory")
template<int NW> __device__ __forceinline__ void cp_wait() {
    asm volatile("cp.async.wait_group %0;" :: "n"(NW) : "memory");
}

// ---------------------------------------------------------------------------
// Row-pointer build: lower_bound over sorted edge_row
// ---------------------------------------------------------------------------
__global__ void rowptr_kernel(const int* __restrict__ edge_row) {
    int i = blockIdx.x * blockDim.x + threadIdx.x;
    if (i > N_NODES) return;
    int lo = 0, hi = E_EDGES;
    while (lo < hi) {
        int mid = (lo + hi) >> 1;
        if (edge_row[mid] < i) lo = mid + 1;
        else hi = mid;
    }
    g_rowptr[i] = lo;
}

// ---------------------------------------------------------------------------
// tf32 tensor-core GEMM, cp.async double-buffered (raw fp32 staged, cvt in regs):
//   out[m][n] = sum_k A[m][k] * W[n][k]
// BM=128, BK=32, 256 threads (8 warps), 2 CTAs/SM.
// Smem rows: 36 floats (144B) stride, conflict-free for fragment LDS.
// ---------------------------------------------------------------------------
template<int N, int K>
__global__ void __launch_bounds__(256, 2) gemm_tf32p(const float* __restrict__ A,
                                                     const float* __restrict__ W,
                                                     float* __restrict__ out, int M) {
    constexpr int BM = 128;
    constexpr int LDSW = 36;                        // floats per smem row
    constexpr int AFLOATS = BM * LDSW;
    constexpr int WFLOATS = N * LDSW;
    constexpr int STAGEF  = AFLOATS + WFLOATS;      // floats per stage
    constexpr int NC = K / 32;
    constexpr int WCOLS = N / 32;
    constexpr int WROWS = 8 / WCOLS;
    constexpr int WTM = BM / WROWS;                 // 64 or 32
    constexpr int MT = WTM / 16;                    // 4 or 2

    extern __shared__ float smem[];
    const uint32_t sb = smem_u32(smem);

    const int tid  = threadIdx.x;
    const int wid  = tid >> 5;
    const int lane = tid & 31;
    const int wm   = (wid / WCOLS) * WTM;
    const int wn   = (wid % WCOLS) * 32;
    const int bm   = blockIdx.x * BM;
    const int arows = min(BM, M - bm);

    const int fr = lane >> 2;
    const int fc = lane & 3;

    float acc[MT][4][4];
#pragma unroll
    for (int i = 0; i < MT; i++)
#pragma unroll
        for (int j = 0; j < 4; j++)
#pragma unroll
            for (int c = 0; c < 4; c++) acc[i][j][c] = 0.f;

    // cp.async stage fill (raw fp32)
    auto fill = [&](int s, int k0) {
        const uint32_t base = sb + (uint32_t)(s * STAGEF * 4);
#pragma unroll
        for (int idx = tid; idx < BM * 8; idx += 256) {      // 4 iters
            int row = idx >> 3, g = idx & 7;
            int sz = (row < arows) ? 16 : 0;
            cp_async16(base + (uint32_t)(row * 144 + g * 16),
                       &A[(size_t)(bm + row) * K + k0 + g * 4], sz);
        }
#pragma unroll
        for (int idx = tid; idx < N * 8; idx += 256) {       // 4 or 2 iters
            int row = idx >> 3, g = idx & 7;
            cp_async16(base + (uint32_t)(AFLOATS * 4 + row * 144 + g * 16),
                       &W[(size_t)row * K + k0 + g * 4], 16);
        }
        CP_COMMIT();
    };

    fill(0, 0);

    for (int kc = 0; kc < NC; kc++) {
        if (kc + 1 < NC) { fill((kc + 1) & 1, (kc + 1) * 32); cp_wait<1>(); }
        else             { cp_wait<0>(); }
        __syncthreads();

        const float* sA = smem + (kc & 1) * STAGEF;
        const float* sW = sA + AFLOATS;

#pragma unroll
        for (int ks = 0; ks < 4; ks++) {
            const int kb = ks * 8 + fc;
            uint32_t af[MT][4];
#pragma unroll
            for (int mt = 0; mt < MT; mt++) {
                int base = (wm + mt * 16 + fr) * LDSW + kb;
                af[mt][0] = f2tf32(sA[base]);
                af[mt][1] = f2tf32(sA[base + 8 * LDSW]);
                af[mt][2] = f2tf32(sA[base + 4]);
                af[mt][3] = f2tf32(sA[base + 8 * LDSW + 4]);
            }
            uint32_t bf[4][2];
#pragma unroll
            for (int nt = 0; nt < 4; nt++) {
                int base = (wn + nt * 8 + fr) * LDSW + kb;
                bf[nt][0] = f2tf32(sW[base]);
                bf[nt][1] = f2tf32(sW[base + 4]);
            }
#pragma unroll
            for (int mt = 0; mt < MT; mt++)
#pragma unroll
                for (int nt = 0; nt < 4; nt++)
                    mma_tf32(acc[mt][nt], af[mt], bf[nt][0], bf[nt][1]);
        }
        __syncthreads();
    }

    // Epilogue
#pragma unroll
    for (int mt = 0; mt < MT; mt++) {
#pragma unroll
        for (int nt = 0; nt < 4; nt++) {
            int r0 = wm + mt * 16 + fr;
            int c0 = wn + nt * 8 + fc * 2;
            if (r0 < arows)
                *reinterpret_cast<float2*>(&out[(size_t)(bm + r0) * N + c0]) =
                    make_float2(acc[mt][nt][0], acc[mt][nt][1]);
            if (r0 + 8 < arows)
                *reinterpret_cast<float2*>(&out[(size_t)(bm + r0 + 8) * N + c0]) =
                    make_float2(acc[mt][nt][2], acc[mt][nt][3]);
        }
    }
}

// ---------------------------------------------------------------------------
// SpMM (H=128): one warp per row, float4 per lane, ReLU
// ---------------------------------------------------------------------------
template<bool RELU>
__global__ void __launch_bounds__(256) spmm128_kernel(const int* __restrict__ edge_col,
                                                      const float* __restrict__ edge_val,
                                                      const float* __restrict__ Z,
                                                      float* __restrict__ out) {
    int gw   = (blockIdx.x * blockDim.x + threadIdx.x) >> 5;
    int lane = threadIdx.x & 31;
    if (gw >= N_NODES) return;
    int s = g_rowptr[gw];
    int e = g_rowptr[gw + 1];

    float4 acc = make_float4(0.f, 0.f, 0.f, 0.f);
    for (int i = s; i < e; i++) {
        int   col = __ldg(&edge_col[i]);
        float val = __ldg(&edge_val[i]);
        float4 z = *reinterpret_cast<const float4*>(&Z[(size_t)col * H_DIM + lane * 4]);
        acc.x = fmaf(val, z.x, acc.x);
        acc.y = fmaf(val, z.y, acc.y);
        acc.z = fmaf(val, z.z, acc.z);
        acc.w = fmaf(val, z.w, acc.w);
    }
    if (RELU) {
        acc.x = fmaxf(acc.x, 0.f);
        acc.y = fmaxf(acc.y, 0.f);
        acc.z = fmaxf(acc.z, 0.f);
        acc.w = fmaxf(acc.w, 0.f);
    }
    *reinterpret_cast<float4*>(&out[(size_t)gw * H_DIM + lane * 4]) = acc;
}

// ---------------------------------------------------------------------------
// Final SpMM (F=64) fused with row softmax
// ---------------------------------------------------------------------------
__global__ void __launch_bounds__(256) spmm64_softmax_kernel(const int* __restrict__ edge_col,
                                                             const float* __restrict__ edge_val,
                                                             const float* __restrict__ Z,
                                                             float* __restrict__ out) {
    int gw   = (blockIdx.x * blockDim.x + threadIdx.x) >> 5;
    int lane = threadIdx.x & 31;
    if (gw >= N_NODES) return;
    int s = g_rowptr[gw];
    int e = g_rowptr[gw + 1];

    float a0 = 0.f, a1 = 0.f;
    for (int i = s; i < e; i++) {
        int   col = __ldg(&edge_col[i]);
        float val = __ldg(&edge_val[i]);
        float2 z = *reinterpret_cast<const float2*>(&Z[(size_t)col * F_DIM + lane * 2]);
        a0 = fmaf(val, z.x, a0);
        a1 = fmaf(val, z.y, a1);
    }
    float m = fmaxf(a0, a1);
#pragma unroll
    for (int off = 16; off > 0; off >>= 1)
        m = fmaxf(m, __shfl_xor_sync(0xFFFFFFFFu, m, off));
    float e0 = expf(a0 - m);
    float e1 = expf(a1 - m);
    float ssum = e0 + e1;
#pragma unroll
    for (int off = 16; off > 0; off >>= 1)
        ssum += __shfl_xor_sync(0xFFFFFFFFu, ssum, off);
    float inv = 1.0f / ssum;
    *reinterpret_cast<float2*>(&out[(size_t)gw * F_DIM + lane * 2]) =
        make_float2(e0 * inv, e1 * inv);
}

// ---------------------------------------------------------------------------
// Launch
// ---------------------------------------------------------------------------
extern "C" void kernel_launch(void* const* d_in, const int* in_sizes, int n_in,
                              void* d_out, int out_size) {
    const float* X        = (const float*)d_in[0];
    const int*   edge_row = (const int*)d_in[1];
    const int*   edge_col = (const int*)d_in[2];
    const float* edge_val = (const float*)d_in[3];
    const float* W0       = (const float*)d_in[4];
    const float* Wh0      = (const float*)d_in[5];
    const float* W1       = (const float*)d_in[6];
    float*       out      = (float*)d_out;

    float *buf1, *buf2;
    cudaGetSymbolAddress((void**)&buf1, g_buf1);
    cudaGetSymbolAddress((void**)&buf2, g_buf2);

    constexpr int SMEM_128 = 2 * (128 + 128) * 144;   // 73728
    constexpr int SMEM_64  = 2 * (128 + 64) * 144;    // 55296
    cudaFuncSetAttribute(gemm_tf32p<128, 256>, cudaFuncAttributeMaxDynamicSharedMemorySize, SMEM_128);
    cudaFuncSetAttribute(gemm_tf32p<128, 128>, cudaFuncAttributeMaxDynamicSharedMemorySize, SMEM_128);
    cudaFuncSetAttribute(gemm_tf32p<64, 128>,  cudaFuncAttributeMaxDynamicSharedMemorySize, SMEM_64);

    const int gemm_grid = (N_NODES + 127) / 128;       // 782
    const int spmm_grid = (N_NODES * 32 + 255) / 256;  // 12500

    rowptr_kernel<<<(N_NODES + 1 + 255) / 256, 256>>>(edge_row);

    // Layer 0: buf1 = X @ W0^T ; buf2 = relu(A @ buf1)
    gemm_tf32p<128, 256><<<gemm_grid, 256, SMEM_128>>>(X, W0, buf1, N_NODES);
    spmm128_kernel<true><<<spmm_grid, 256>>>(edge_col, edge_val, buf1, buf2);

    // Hidden: buf1 = buf2 @ Wh0^T ; buf2 = relu(A @ buf1)
    gemm_tf32p<128, 128><<<gemm_grid, 256, SMEM_128>>>(buf2, Wh0, buf1, N_NODES);
    spmm128_kernel<true><<<spmm_grid, 256>>>(edge_col, edge_val, buf1, buf2);

    // Output: buf1 = buf2 @ W1^T ; out = softmax(A @ buf1)
    gemm_tf32p<64, 128><<<gemm_grid, 256, SMEM_64>>>(buf2, W1, buf1, N_NODES);
    spmm64_softmax_kernel<<<spmm_grid, 256>>>(edge_col, edge_val, buf1, out);
}